// round 12
// baseline (speedup 1.0000x reference)
#include <cuda_runtime.h>
#include <cuda_bf16.h>
#include <cuda.h>
#include <cstdint>

#define N 2048
#define NB 8
#define NN (N * N)

// ---------------- GEMM tiling ----------------
#define BM 128
#define BN 256
#define BK 64                     // 64 bf16 = 128 B rows (SW128)
#define NT (N / BK)               // 32 k-tiles
#define OFF_AL 16384              // A tile = 128 rows * 128 B
#define OFF_BH 32768
#define OFF_BL 65536              // B tile = 256 rows * 128 B
#define STAGEB 98304
#define SMEM_GEMM (2 * STAGEB)    // 196608 B, 2-stage ping-pong

// ---------------- device scratch ----------------
__device__ float g_A2[(size_t)NB * NN];
__device__ float g_A3[(size_t)NB * NN];
__device__ float g_A4[(size_t)NB * NN];
__device__ __nv_bfloat16 g_Ah  [(size_t)NB * NN];
__device__ __nv_bfloat16 g_Al  [(size_t)NB * NN];
__device__ __nv_bfloat16 g_AhT [(size_t)NB * NN];
__device__ __nv_bfloat16 g_AlT [(size_t)NB * NN];
__device__ __nv_bfloat16 g_A2h [(size_t)NB * NN];
__device__ __nv_bfloat16 g_A2l [(size_t)NB * NN];
__device__ __nv_bfloat16 g_A2hT[(size_t)NB * NN];
__device__ __nv_bfloat16 g_A2lT[(size_t)NB * NN];
__device__ float g_D[7 * NB * N];

// ---------------- helpers ----------------
__device__ __forceinline__ uint32_t s2u(const void* p) {
    uint32_t a;
    asm("{ .reg .u64 t; cvta.to.shared.u64 t, %1; cvt.u32.u64 %0, t; }" : "=r"(a) : "l"(p));
    return a;
}

#define LDSM4(r0, r1, r2, r3, a)                                              \
    asm volatile("ldmatrix.sync.aligned.m8n8.x4.shared.b16 {%0,%1,%2,%3}, [%4];" \
                 : "=r"(r0), "=r"(r1), "=r"(r2), "=r"(r3) : "r"(a))

__device__ __forceinline__ void mma16816(float* c, const uint32_t* a, const uint32_t* b) {
    asm volatile(
        "mma.sync.aligned.m16n8k16.row.col.f32.bf16.bf16.f32 "
        "{%0,%1,%2,%3}, {%4,%5,%6,%7}, {%8,%9}, {%0,%1,%2,%3};"
        : "+f"(c[0]), "+f"(c[1]), "+f"(c[2]), "+f"(c[3])
        : "r"(a[0]), "r"(a[1]), "r"(a[2]), "r"(a[3]), "r"(b[0]), "r"(b[1]));
}

#define MBARRIER_INIT(addr, cnt) \
    asm volatile("mbarrier.init.shared.b64 [%0], %1;" :: "r"(addr), "r"((uint32_t)(cnt)) : "memory")
#define MBARRIER_EXPECT_TX(addr, bytes) \
    asm volatile("mbarrier.arrive.expect_tx.shared.b64 _, [%0], %1;" \
                 :: "r"(addr), "r"((uint32_t)(bytes)) : "memory")
#define MBAR_WAIT(addr, ph) do {                                              \
    asm volatile(                                                             \
        "{\n\t.reg .pred P1;\n\t"                                             \
        "WL_%=:\n\t"                                                          \
        "mbarrier.try_wait.parity.acquire.cta.shared::cta.b64 P1, [%0], %1, 0x989680;\n\t" \
        "@P1 bra.uni WD_%=;\n\t"                                              \
        "bra.uni WL_%=;\n\t"                                                  \
        "WD_%=:\n\t}"                                                         \
        :: "r"(addr), "r"((uint32_t)(ph)) : "memory");                        \
} while (0)

#define TMA_LOAD_3D(smem_addr, tmap, cx, cy, cz, mbar)                        \
    asm volatile(                                                             \
        "cp.async.bulk.tensor.3d.shared::cta.global.tile.mbarrier::complete_tx::bytes " \
        "[%0], [%1, {%2, %3, %4}], [%5];"                                     \
        :: "r"((uint32_t)(smem_addr)), "l"(tmap), "r"((int32_t)(cx)),         \
           "r"((int32_t)(cy)), "r"((int32_t)(cz)), "r"((uint32_t)(mbar))      \
        : "memory")

__device__ __forceinline__ uint32_t pack_bf2(__nv_bfloat16 a, __nv_bfloat16 b) {
    return (uint32_t)__bfloat16_as_ushort(a) | ((uint32_t)__bfloat16_as_ushort(b) << 16);
}

// ---------------------------------------------------------------------------
// bf16-split HMMA GEMM with TMA double-buffering (R10 mainloop, at MMA floor).
// ---------------------------------------------------------------------------
__global__ __launch_bounds__(256, 1) void gemm_tma(
    const __grid_constant__ CUtensorMap tAh,
    const __grid_constant__ CUtensorMap tAl,
    const __grid_constant__ CUtensorMap tBh,
    const __grid_constant__ CUtensorMap tBl,
    float* __restrict__ C)
{
    extern __shared__ __align__(1024) char smem[];
    __shared__ __align__(8) uint64_t mbar[2];

    const int tid = threadIdx.x;
    const int b  = blockIdx.z;
    const int m0 = blockIdx.y * BM;
    const int n0 = blockIdx.x * BN;
    const uint32_t sbase = s2u(smem);
    const uint32_t barb  = s2u(mbar);

    const int wid = tid >> 5, lane = tid & 31;
    const int wm = wid & 1;
    const int wn = wid >> 1;
    const int a_row = lane & 15;
    const int a_cb  = lane >> 4;
    const int b_row = ((lane >> 4) << 3) + (lane & 7);
    const int b_cb  = (lane >> 3) & 1;
    const uint32_t rx7 = (uint32_t)(lane & 7);

    if (tid == 0) {
        MBARRIER_INIT(barb, 1);
        MBARRIER_INIT(barb + 8, 1);
    }
    __syncthreads();

    auto issue_stage = [&](int kt, int buf) {
        const uint32_t fullb = barb + 8 * buf;
        const uint32_t sb = sbase + buf * STAGEB;
        const int k0 = kt * BK;
        MBARRIER_EXPECT_TX(fullb, STAGEB);
        TMA_LOAD_3D(sb,           &tAh, k0, m0, b, fullb);
        TMA_LOAD_3D(sb + OFF_AL,  &tAl, k0, m0, b, fullb);
        TMA_LOAD_3D(sb + OFF_BH,  &tBh, k0, n0, b, fullb);
        TMA_LOAD_3D(sb + OFF_BL,  &tBl, k0, n0, b, fullb);
    };

    if (tid == 0) {
        issue_stage(0, 0);
        issue_stage(1, 1);
    }

    float acc[4][8][4];
#pragma unroll
    for (int mi = 0; mi < 4; mi++)
#pragma unroll
        for (int ni = 0; ni < 8; ni++)
#pragma unroll
            for (int q = 0; q < 4; q++) acc[mi][ni][q] = 0.0f;

    uint32_t ah[4][4], al[4][4], bh[8][2], bl[8][2];

    const uint32_t rowA = (uint32_t)(wm * 64 + a_row) * 128;
    const uint32_t rowB = (uint32_t)(wn * 64 + b_row) * 128;

    for (int kt = 0; kt < NT; kt++) {
        const int buf = kt & 1;
        MBAR_WAIT(barb + 8 * buf, (kt >> 1) & 1);
        const uint32_t sb = sbase + buf * STAGEB;

#pragma unroll
        for (int ks = 0; ks < 4; ks++) {
            const uint32_t cxa = (uint32_t)((ks * 2 + a_cb) ^ rx7) * 16;
            const uint32_t cxb = (uint32_t)((ks * 2 + b_cb) ^ rx7) * 16;
#pragma unroll
            for (int mi = 0; mi < 4; mi++) {
                const uint32_t ra = sb + rowA + (uint32_t)(mi * 16) * 128 + cxa;
                LDSM4(ah[mi][0], ah[mi][1], ah[mi][2], ah[mi][3], ra);
                LDSM4(al[mi][0], al[mi][1], al[mi][2], al[mi][3], ra + OFF_AL);
            }
#pragma unroll
            for (int nj = 0; nj < 4; nj++) {
                const uint32_t rb = sb + OFF_BH + rowB + (uint32_t)(nj * 16) * 128 + cxb;
                LDSM4(bh[2 * nj][0], bh[2 * nj][1], bh[2 * nj + 1][0], bh[2 * nj + 1][1], rb);
                LDSM4(bl[2 * nj][0], bl[2 * nj][1], bl[2 * nj + 1][0], bl[2 * nj + 1][1],
                      rb + (OFF_BL - OFF_BH));
            }
            if (ks == 3) {
                __syncthreads();
                if (tid == 0 && kt + 2 < NT) issue_stage(kt + 2, buf);
            }
#pragma unroll
            for (int mi = 0; mi < 4; mi++)
#pragma unroll
                for (int ni = 0; ni < 8; ni++) {
                    mma16816(acc[mi][ni], ah[mi], bh[ni]);   // hi*hi
                    mma16816(acc[mi][ni], ah[mi], bl[ni]);   // hi*lo
                    mma16816(acc[mi][ni], al[mi], bh[ni]);   // lo*hi
                }
        }
    }

    // epilogue
    float* Cb = C + (size_t)b * NN;
#pragma unroll
    for (int mi = 0; mi < 4; mi++) {
        const int rg = m0 + wm * 64 + mi * 16 + (lane >> 2);
#pragma unroll
        for (int ni = 0; ni < 8; ni++) {
            const int cg = n0 + wn * 64 + ni * 8 + (lane & 3) * 2;
            float* p = Cb + (size_t)rg * N + cg;
            *(float2*)p           = make_float2(acc[mi][ni][0], acc[mi][ni][1]);
            *(float2*)(p + 8 * N) = make_float2(acc[mi][ni][2], acc[mi][ni][3]);
        }
    }
}

// ---------------------------------------------------------------------------
// fused split + transpose-split, vectorized: 64x64 tiles, float2 loads,
// packed 2xbf16 (uint32) stores for all four outputs.
// ---------------------------------------------------------------------------
__global__ __launch_bounds__(256) void split_both_kernel(
    const float* __restrict__ X,
    __nv_bfloat16* __restrict__ H,  __nv_bfloat16* __restrict__ L,
    __nv_bfloat16* __restrict__ HT, __nv_bfloat16* __restrict__ LT)
{
    __shared__ float t[64][65];
    const int b = blockIdx.z;
    const int r0 = blockIdx.y * 64;
    const int c0 = blockIdx.x * 64;
    const int tx = threadIdx.x;   // 0..31
    const int ty = threadIdx.y;   // 0..7
    const float* Xb = X + (size_t)b * NN;

#pragma unroll
    for (int i = 0; i < 8; i++) {
        const int row = r0 + ty + 8 * i;
        const float2 v = *(const float2*)(Xb + (size_t)row * N + c0 + 2 * tx);
        t[ty + 8 * i][2 * tx]     = v.x;
        t[ty + 8 * i][2 * tx + 1] = v.y;
        const __nv_bfloat16 h0 = __float2bfloat16(v.x);
        const __nv_bfloat16 h1 = __float2bfloat16(v.y);
        const __nv_bfloat16 l0 = __float2bfloat16(v.x - __bfloat162float(h0));
        const __nv_bfloat16 l1 = __float2bfloat16(v.y - __bfloat162float(h1));
        const size_t o = (size_t)b * NN + (size_t)row * N + c0 + 2 * tx;
        *(uint32_t*)(H + o) = pack_bf2(h0, h1);
        *(uint32_t*)(L + o) = pack_bf2(l0, l1);
    }
    __syncthreads();
#pragma unroll
    for (int i = 0; i < 8; i++) {
        const int cc = ty + 8 * i;
        const float v0 = t[2 * tx][cc];
        const float v1 = t[2 * tx + 1][cc];
        const __nv_bfloat16 h0 = __float2bfloat16(v0);
        const __nv_bfloat16 h1 = __float2bfloat16(v1);
        const __nv_bfloat16 l0 = __float2bfloat16(v0 - __bfloat162float(h0));
        const __nv_bfloat16 l1 = __float2bfloat16(v1 - __bfloat162float(h1));
        const size_t o = (size_t)b * NN + (size_t)(c0 + cc) * N + r0 + 2 * tx;
        *(uint32_t*)(HT + o) = pack_bf2(h0, h1);
        *(uint32_t*)(LT + o) = pack_bf2(l0, l1);
    }
}

// ---------------------------------------------------------------------------
// zero g_D
// ---------------------------------------------------------------------------
__global__ void zeroD_kernel() {
    const int i = blockIdx.x * blockDim.x + threadIdx.x;
    if (i < 7 * NB * N) g_D[i] = 0.0f;
}

// ---------------------------------------------------------------------------
// diag pair-products, k-split x4 with atomic accumulation
// ---------------------------------------------------------------------------
#define KSPLIT 4
__global__ __launch_bounds__(256) void diag_kernel(const float* __restrict__ A)
{
    const int b = blockIdx.y;
    const int n0 = blockIdx.x * 32;
    const int kz = blockIdx.z;
    const float* Ab  = A    + (size_t)b * NN;
    const float* A2b = g_A2 + (size_t)b * NN;
    const float* A3b = g_A3 + (size_t)b * NN;
    const float* A4b = g_A4 + (size_t)b * NN;

    __shared__ float xr[3][32][33];
    __shared__ float yc[4][32][33];
    __shared__ float red[7][8][32];

    const int tid = threadIdx.x;
    const int r = tid >> 5;
    const int c = tid & 31;

    float acc[7];
#pragma unroll
    for (int p = 0; p < 7; p++) acc[p] = 0.0f;

    const int kbeg = kz * (N / KSPLIT);
    const int kend = kbeg + N / KSPLIT;
    for (int k0 = kbeg; k0 < kend; k0 += 32) {
#pragma unroll
        for (int l = 0; l < 4; l++) {
            const int i = r + 8 * l;
            xr[0][i][c] = Ab [(size_t)(n0 + i) * N + k0 + c];
            xr[1][i][c] = A2b[(size_t)(n0 + i) * N + k0 + c];
            xr[2][i][c] = A4b[(size_t)(n0 + i) * N + k0 + c];
            yc[0][c][i] = Ab [(size_t)(k0 + i) * N + n0 + c];
            yc[1][c][i] = A2b[(size_t)(k0 + i) * N + n0 + c];
            yc[2][c][i] = A3b[(size_t)(k0 + i) * N + n0 + c];
            yc[3][c][i] = A4b[(size_t)(k0 + i) * N + n0 + c];
        }
        __syncthreads();

#pragma unroll
        for (int q = 0; q < 4; q++) {
            const int kk = r * 4 + q;
            const float a   = xr[0][c][kk];
            const float a2  = xr[1][c][kk];
            const float a4  = xr[2][c][kk];
            const float ca  = yc[0][c][kk];
            const float ca2 = yc[1][c][kk];
            const float ca3 = yc[2][c][kk];
            const float ca4 = yc[3][c][kk];
            acc[0] = fmaf(a,  ca,  acc[0]);
            acc[1] = fmaf(a2, ca,  acc[1]);
            acc[2] = fmaf(a2, ca2, acc[2]);
            acc[3] = fmaf(a4, ca,  acc[3]);
            acc[4] = fmaf(a4, ca2, acc[4]);
            acc[5] = fmaf(a4, ca3, acc[5]);
            acc[6] = fmaf(a4, ca4, acc[6]);
        }
        __syncthreads();
    }

#pragma unroll
    for (int p = 0; p < 7; p++) red[p][r][c] = acc[p];
    __syncthreads();

    if (r == 0) {
#pragma unroll
        for (int p = 0; p < 7; p++) {
            float s = 0.0f;
#pragma unroll
            for (int rr = 0; rr < 8; rr++) s += red[p][rr][c];
            atomicAdd(&g_D[(size_t)p * NB * N + (size_t)b * N + n0 + c], s);
        }
    }
}

__global__ __launch_bounds__(256) void combine_kernel(
    const float* __restrict__ A, const float* __restrict__ h,
    float* __restrict__ out)
{
    const int idx = blockIdx.x * blockDim.x + threadIdx.x;
    if (idx >= NB * N * 64) return;
    const int c = idx & 63;
    const int n = (idx >> 6) & (N - 1);
    const int b = idx >> 17;

    const float d1 = A[(size_t)b * NN + (size_t)n * N + n];
    float v = h[c] + h[64 + c] * d1;
#pragma unroll
    for (int t = 2; t <= 8; t++) {
        const float dt = g_D[(size_t)(t - 2) * NB * N + (size_t)b * N + n];
        v = fmaf(h[t * 64 + c], dt, v);
    }
    out[idx] = v;
}

// ---------------------------------------------------------------------------
// host
// ---------------------------------------------------------------------------
typedef CUresult (*PFN_tmap_encode)(
    CUtensorMap*, CUtensorMapDataType, cuuint32_t, void*,
    const cuuint64_t*, const cuuint64_t*, const cuuint32_t*, const cuuint32_t*,
    CUtensorMapInterleave, CUtensorMapSwizzle, CUtensorMapL2promotion,
    CUtensorMapFloatOOBfill);

static CUtensorMap make_map(PFN_tmap_encode enc, void* ptr, uint32_t box_rows) {
    CUtensorMap m{};
    cuuint64_t dims[3]    = {N, N, NB};
    cuuint64_t strides[2] = {(cuuint64_t)N * 2, (cuuint64_t)NN * 2};
    cuuint32_t box[3]     = {BK, box_rows, 1};
    cuuint32_t es[3]      = {1, 1, 1};
    enc(&m, CU_TENSOR_MAP_DATA_TYPE_BFLOAT16, 3, ptr, dims, strides, box, es,
        CU_TENSOR_MAP_INTERLEAVE_NONE, CU_TENSOR_MAP_SWIZZLE_128B,
        CU_TENSOR_MAP_L2_PROMOTION_L2_128B, CU_TENSOR_MAP_FLOAT_OOB_FILL_NONE);
    return m;
}

extern "C" void kernel_launch(void* const* d_in, const int* in_sizes, int n_in,
                              void* d_out, int out_size)
{
    const float* A = (const float*)d_in[0];   // [8, 2048, 2048]
    const float* h = (const float*)d_in[1];   // [9, 64]
    float* out = (float*)d_out;               // [8, 2048, 64]

    void *A2, *A3, *A4, *Ah, *Al, *AhT, *AlT, *A2h, *A2l, *A2hT, *A2lT;
    cudaGetSymbolAddress(&A2, g_A2);   cudaGetSymbolAddress(&A3, g_A3);
    cudaGetSymbolAddress(&A4, g_A4);
    cudaGetSymbolAddress(&Ah, g_Ah);   cudaGetSymbolAddress(&Al, g_Al);
    cudaGetSymbolAddress(&AhT, g_AhT); cudaGetSymbolAddress(&AlT, g_AlT);
    cudaGetSymbolAddress(&A2h, g_A2h); cudaGetSymbolAddress(&A2l, g_A2l);
    cudaGetSymbolAddress(&A2hT, g_A2hT); cudaGetSymbolAddress(&A2lT, g_A2lT);

    PFN_tmap_encode enc = nullptr;
    {
        void* fn = nullptr;
        cudaDriverEntryPointQueryResult qr;
        cudaGetDriverEntryPoint("cuTensorMapEncodeTiled", &fn,
                                cudaEnableDefault, &qr);
        enc = (PFN_tmap_encode)fn;
    }
    if (!enc) return;

    const CUtensorMap mAh   = make_map(enc, Ah,   BM);
    const CUtensorMap mAl   = make_map(enc, Al,   BM);
    const CUtensorMap mAhT  = make_map(enc, AhT,  BN);
    const CUtensorMap mAlT  = make_map(enc, AlT,  BN);
    const CUtensorMap mA2h  = make_map(enc, A2h,  BM);
    const CUtensorMap mA2l  = make_map(enc, A2l,  BM);
    const CUtensorMap mA2hT = make_map(enc, A2hT, BN);
    const CUtensorMap mA2lT = make_map(enc, A2lT, BN);

    cudaFuncSetAttribute(gemm_tma,
                         cudaFuncAttributeMaxDynamicSharedMemorySize, SMEM_GEMM);

    zeroD_kernel<<<(7 * NB * N + 255) / 256, 256>>>();

    split_both_kernel<<<dim3(N / 64, N / 64, NB), dim3(32, 8)>>>(
        A, (__nv_bfloat16*)Ah, (__nv_bfloat16*)Al,
        (__nv_bfloat16*)AhT, (__nv_bfloat16*)AlT);

    const dim3 gg(N / BN, N / BM, NB);
    // A2 = A @ A
    gemm_tma<<<gg, 256, SMEM_GEMM>>>(mAh, mAl, mAhT, mAlT, (float*)A2);

    split_both_kernel<<<dim3(N / 64, N / 64, NB), dim3(32, 8)>>>(
        (const float*)A2, (__nv_bfloat16*)A2h, (__nv_bfloat16*)A2l,
        (__nv_bfloat16*)A2hT, (__nv_bfloat16*)A2lT);

    // A3 = A2 @ A
    gemm_tma<<<gg, 256, SMEM_GEMM>>>(mA2h, mA2l, mAhT, mAlT, (float*)A3);
    // A4 = A2 @ A2
    gemm_tma<<<gg, 256, SMEM_GEMM>>>(mA2h, mA2l, mA2hT, mA2lT, (float*)A4);

    diag_kernel<<<dim3(N / 32, NB, KSPLIT), 256>>>(A);

    const int total = NB * N * 64;
    combine_kernel<<<(total + 255) / 256, 256>>>(A, h, out);
}

// round 14
// speedup vs baseline: 1.0015x; 1.0015x over previous
#include <cuda_runtime.h>
#include <cuda_bf16.h>
#include <cuda.h>
#include <cstdint>

#define N 2048
#define NB 8
#define NN (N * N)

// ---------------- GEMM tiling ----------------
#define BM 128
#define BN 256
#define BK 64                     // 64 bf16 = 128 B rows (SW128)
#define NT (N / BK)               // 32 k-tiles
#define OFF_AL 16384              // A tile = 128 rows * 128 B
#define OFF_BH 32768
#define OFF_BL 65536              // B tile = 256 rows * 128 B
#define STAGEB 98304
#define SMEM_GEMM (2 * STAGEB)    // 196608 B, 2-stage ping-pong

// ---------------- device scratch ----------------
__device__ float g_A2[(size_t)NB * NN];
__device__ float g_A3[(size_t)NB * NN];
__device__ float g_A4[(size_t)NB * NN];
__device__ __nv_bfloat16 g_Ah  [(size_t)NB * NN];
__device__ __nv_bfloat16 g_Al  [(size_t)NB * NN];
__device__ __nv_bfloat16 g_AhT [(size_t)NB * NN];
__device__ __nv_bfloat16 g_AlT [(size_t)NB * NN];
__device__ __nv_bfloat16 g_A2h [(size_t)NB * NN];
__device__ __nv_bfloat16 g_A2l [(size_t)NB * NN];
__device__ __nv_bfloat16 g_A2hT[(size_t)NB * NN];
__device__ __nv_bfloat16 g_A2lT[(size_t)NB * NN];
__device__ float g_D[7 * NB * N];

// ---------------- helpers ----------------
__device__ __forceinline__ uint32_t s2u(const void* p) {
    uint32_t a;
    asm("{ .reg .u64 t; cvta.to.shared.u64 t, %1; cvt.u32.u64 %0, t; }" : "=r"(a) : "l"(p));
    return a;
}

#define LDSM4(r0, r1, r2, r3, a)                                              \
    asm volatile("ldmatrix.sync.aligned.m8n8.x4.shared.b16 {%0,%1,%2,%3}, [%4];" \
                 : "=r"(r0), "=r"(r1), "=r"(r2), "=r"(r3) : "r"(a))

__device__ __forceinline__ void mma16816(float* c, const uint32_t* a, const uint32_t* b) {
    asm volatile(
        "mma.sync.aligned.m16n8k16.row.col.f32.bf16.bf16.f32 "
        "{%0,%1,%2,%3}, {%4,%5,%6,%7}, {%8,%9}, {%0,%1,%2,%3};"
        : "+f"(c[0]), "+f"(c[1]), "+f"(c[2]), "+f"(c[3])
        : "r"(a[0]), "r"(a[1]), "r"(a[2]), "r"(a[3]), "r"(b[0]), "r"(b[1]));
}

#define MBARRIER_INIT(addr, cnt) \
    asm volatile("mbarrier.init.shared.b64 [%0], %1;" :: "r"(addr), "r"((uint32_t)(cnt)) : "memory")
#define MBARRIER_EXPECT_TX(addr, bytes) \
    asm volatile("mbarrier.arrive.expect_tx.shared.b64 _, [%0], %1;" \
                 :: "r"(addr), "r"((uint32_t)(bytes)) : "memory")
#define MBAR_WAIT(addr, ph) do {                                              \
    asm volatile(                                                             \
        "{\n\t.reg .pred P1;\n\t"                                             \
        "WL_%=:\n\t"                                                          \
        "mbarrier.try_wait.parity.acquire.cta.shared::cta.b64 P1, [%0], %1, 0x989680;\n\t" \
        "@P1 bra.uni WD_%=;\n\t"                                              \
        "bra.uni WL_%=;\n\t"                                                  \
        "WD_%=:\n\t}"                                                         \
        :: "r"(addr), "r"((uint32_t)(ph)) : "memory");                        \
} while (0)

#define TMA_LOAD_3D(smem_addr, tmap, cx, cy, cz, mbar)                        \
    asm volatile(                                                             \
        "cp.async.bulk.tensor.3d.shared::cta.global.tile.mbarrier::complete_tx::bytes " \
        "[%0], [%1, {%2, %3, %4}], [%5];"                                     \
        :: "r"((uint32_t)(smem_addr)), "l"(tmap), "r"((int32_t)(cx)),         \
           "r"((int32_t)(cy)), "r"((int32_t)(cz)), "r"((uint32_t)(mbar))      \
        : "memory")

__device__ __forceinline__ uint32_t pack_bf2(__nv_bfloat16 a, __nv_bfloat16 b) {
    return (uint32_t)__bfloat16_as_ushort(a) | ((uint32_t)__bfloat16_as_ushort(b) << 16);
}

// ---------------------------------------------------------------------------
// bf16-split HMMA GEMM with TMA double-buffering (R10 mainloop, at MMA floor).
// ---------------------------------------------------------------------------
__global__ __launch_bounds__(256, 1) void gemm_tma(
    const __grid_constant__ CUtensorMap tAh,
    const __grid_constant__ CUtensorMap tAl,
    const __grid_constant__ CUtensorMap tBh,
    const __grid_constant__ CUtensorMap tBl,
    float* __restrict__ C)
{
    extern __shared__ __align__(1024) char smem[];
    __shared__ __align__(8) uint64_t mbar[2];

    const int tid = threadIdx.x;
    const int b  = blockIdx.z;
    const int m0 = blockIdx.y * BM;
    const int n0 = blockIdx.x * BN;
    const uint32_t sbase = s2u(smem);
    const uint32_t barb  = s2u(mbar);

    const int wid = tid >> 5, lane = tid & 31;
    const int wm = wid & 1;
    const int wn = wid >> 1;
    const int a_row = lane & 15;
    const int a_cb  = lane >> 4;
    const int b_row = ((lane >> 4) << 3) + (lane & 7);
    const int b_cb  = (lane >> 3) & 1;
    const uint32_t rx7 = (uint32_t)(lane & 7);

    if (tid == 0) {
        MBARRIER_INIT(barb, 1);
        MBARRIER_INIT(barb + 8, 1);
    }
    __syncthreads();

    auto issue_stage = [&](int kt, int buf) {
        const uint32_t fullb = barb + 8 * buf;
        const uint32_t sb = sbase + buf * STAGEB;
        const int k0 = kt * BK;
        MBARRIER_EXPECT_TX(fullb, STAGEB);
        TMA_LOAD_3D(sb,           &tAh, k0, m0, b, fullb);
        TMA_LOAD_3D(sb + OFF_AL,  &tAl, k0, m0, b, fullb);
        TMA_LOAD_3D(sb + OFF_BH,  &tBh, k0, n0, b, fullb);
        TMA_LOAD_3D(sb + OFF_BL,  &tBl, k0, n0, b, fullb);
    };

    if (tid == 0) {
        issue_stage(0, 0);
        issue_stage(1, 1);
    }

    float acc[4][8][4];
#pragma unroll
    for (int mi = 0; mi < 4; mi++)
#pragma unroll
        for (int ni = 0; ni < 8; ni++)
#pragma unroll
            for (int q = 0; q < 4; q++) acc[mi][ni][q] = 0.0f;

    uint32_t ah[4][4], al[4][4], bh[8][2], bl[8][2];

    const uint32_t rowA = (uint32_t)(wm * 64 + a_row) * 128;
    const uint32_t rowB = (uint32_t)(wn * 64 + b_row) * 128;

    for (int kt = 0; kt < NT; kt++) {
        const int buf = kt & 1;
        MBAR_WAIT(barb + 8 * buf, (kt >> 1) & 1);
        const uint32_t sb = sbase + buf * STAGEB;

#pragma unroll
        for (int ks = 0; ks < 4; ks++) {
            const uint32_t cxa = (uint32_t)((ks * 2 + a_cb) ^ rx7) * 16;
            const uint32_t cxb = (uint32_t)((ks * 2 + b_cb) ^ rx7) * 16;
#pragma unroll
            for (int mi = 0; mi < 4; mi++) {
                const uint32_t ra = sb + rowA + (uint32_t)(mi * 16) * 128 + cxa;
                LDSM4(ah[mi][0], ah[mi][1], ah[mi][2], ah[mi][3], ra);
                LDSM4(al[mi][0], al[mi][1], al[mi][2], al[mi][3], ra + OFF_AL);
            }
#pragma unroll
            for (int nj = 0; nj < 4; nj++) {
                const uint32_t rb = sb + OFF_BH + rowB + (uint32_t)(nj * 16) * 128 + cxb;
                LDSM4(bh[2 * nj][0], bh[2 * nj][1], bh[2 * nj + 1][0], bh[2 * nj + 1][1], rb);
                LDSM4(bl[2 * nj][0], bl[2 * nj][1], bl[2 * nj + 1][0], bl[2 * nj + 1][1],
                      rb + (OFF_BL - OFF_BH));
            }
            if (ks == 3) {
                __syncthreads();
                if (tid == 0 && kt + 2 < NT) issue_stage(kt + 2, buf);
            }
#pragma unroll
            for (int mi = 0; mi < 4; mi++)
#pragma unroll
                for (int ni = 0; ni < 8; ni++) {
                    mma16816(acc[mi][ni], ah[mi], bh[ni]);   // hi*hi
                    mma16816(acc[mi][ni], ah[mi], bl[ni]);   // hi*lo
                    mma16816(acc[mi][ni], al[mi], bh[ni]);   // lo*hi
                }
        }
    }

    // epilogue
    float* Cb = C + (size_t)b * NN;
#pragma unroll
    for (int mi = 0; mi < 4; mi++) {
        const int rg = m0 + wm * 64 + mi * 16 + (lane >> 2);
#pragma unroll
        for (int ni = 0; ni < 8; ni++) {
            const int cg = n0 + wn * 64 + ni * 8 + (lane & 3) * 2;
            float* p = Cb + (size_t)rg * N + cg;
            *(float2*)p           = make_float2(acc[mi][ni][0], acc[mi][ni][1]);
            *(float2*)(p + 8 * N) = make_float2(acc[mi][ni][2], acc[mi][ni][3]);
        }
    }
}

// ---------------------------------------------------------------------------
// fused split + transpose-split, vectorized: 64x64 tiles, float2 loads,
// packed 2xbf16 (uint32) stores for all four outputs.
// ---------------------------------------------------------------------------
__global__ __launch_bounds__(256) void split_both_kernel(
    const float* __restrict__ X,
    __nv_bfloat16* __restrict__ H,  __nv_bfloat16* __restrict__ L,
    __nv_bfloat16* __restrict__ HT, __nv_bfloat16* __restrict__ LT)
{
    __shared__ float t[64][65];
    const int b = blockIdx.z;
    const int r0 = blockIdx.y * 64;
    const int c0 = blockIdx.x * 64;
    const int tx = threadIdx.x;   // 0..31
    const int ty = threadIdx.y;   // 0..7
    const float* Xb = X + (size_t)b * NN;

#pragma unroll
    for (int i = 0; i < 8; i++) {
        const int row = r0 + ty + 8 * i;
        const float2 v = *(const float2*)(Xb + (size_t)row * N + c0 + 2 * tx);
        t[ty + 8 * i][2 * tx]     = v.x;
        t[ty + 8 * i][2 * tx + 1] = v.y;
        const __nv_bfloat16 h0 = __float2bfloat16(v.x);
        const __nv_bfloat16 h1 = __float2bfloat16(v.y);
        const __nv_bfloat16 l0 = __float2bfloat16(v.x - __bfloat162float(h0));
        const __nv_bfloat16 l1 = __float2bfloat16(v.y - __bfloat162float(h1));
        const size_t o = (size_t)b * NN + (size_t)row * N + c0 + 2 * tx;
        *(uint32_t*)(H + o) = pack_bf2(h0, h1);
        *(uint32_t*)(L + o) = pack_bf2(l0, l1);
    }
    __syncthreads();
#pragma unroll
    for (int i = 0; i < 8; i++) {
        const int cc = ty + 8 * i;
        const float v0 = t[2 * tx][cc];
        const float v1 = t[2 * tx + 1][cc];
        const __nv_bfloat16 h0 = __float2bfloat16(v0);
        const __nv_bfloat16 h1 = __float2bfloat16(v1);
        const __nv_bfloat16 l0 = __float2bfloat16(v0 - __bfloat162float(h0));
        const __nv_bfloat16 l1 = __float2bfloat16(v1 - __bfloat162float(h1));
        const size_t o = (size_t)b * NN + (size_t)(c0 + cc) * N + r0 + 2 * tx;
        *(uint32_t*)(HT + o) = pack_bf2(h0, h1);
        *(uint32_t*)(LT + o) = pack_bf2(l0, l1);
    }
}

// ---------------------------------------------------------------------------
// zero g_D
// ---------------------------------------------------------------------------
__global__ void zeroD_kernel() {
    const int i = blockIdx.x * blockDim.x + threadIdx.x;
    if (i < 7 * NB * N) g_D[i] = 0.0f;
}

// ---------------------------------------------------------------------------
// diag pair-products, 6-stream pairing:
//   d2=<A,A>  d3=<A2,A>  d4=<A3,A>  d5=<A4,A>  d6=<A2,A4>  d7=<A3,A4>  d8=<A4,A4>
// rows{A,A2,A3,A4} + cols{A,A4}: 768MB total traffic (was 896MB).
// k-split x4 with atomic accumulation.
// ---------------------------------------------------------------------------
#define KSPLIT 4
__global__ __launch_bounds__(256) void diag_kernel(const float* __restrict__ A)
{
    const int b = blockIdx.y;
    const int n0 = blockIdx.x * 32;
    const int kz = blockIdx.z;
    const float* Ab  = A    + (size_t)b * NN;
    const float* A2b = g_A2 + (size_t)b * NN;
    const float* A3b = g_A3 + (size_t)b * NN;
    const float* A4b = g_A4 + (size_t)b * NN;

    __shared__ float xr[4][32][33];   // rows of A, A2, A3, A4
    __shared__ float yc[2][32][33];   // cols of A, A4 (transposed)
    __shared__ float red[7][8][32];

    const int tid = threadIdx.x;
    const int r = tid >> 5;
    const int c = tid & 31;

    float acc[7];
#pragma unroll
    for (int p = 0; p < 7; p++) acc[p] = 0.0f;

    const int kbeg = kz * (N / KSPLIT);
    const int kend = kbeg + N / KSPLIT;
    for (int k0 = kbeg; k0 < kend; k0 += 32) {
#pragma unroll
        for (int l = 0; l < 4; l++) {
            const int i = r + 8 * l;
            xr[0][i][c] = Ab [(size_t)(n0 + i) * N + k0 + c];
            xr[1][i][c] = A2b[(size_t)(n0 + i) * N + k0 + c];
            xr[2][i][c] = A3b[(size_t)(n0 + i) * N + k0 + c];
            xr[3][i][c] = A4b[(size_t)(n0 + i) * N + k0 + c];
            yc[0][c][i] = Ab [(size_t)(k0 + i) * N + n0 + c];
            yc[1][c][i] = A4b[(size_t)(k0 + i) * N + n0 + c];
        }
        __syncthreads();

#pragma unroll
        for (int q = 0; q < 4; q++) {
            const int kk = r * 4 + q;
            const float a   = xr[0][c][kk];
            const float a2  = xr[1][c][kk];
            const float a3  = xr[2][c][kk];
            const float a4  = xr[3][c][kk];
            const float ca  = yc[0][c][kk];
            const float ca4 = yc[1][c][kk];
            acc[0] = fmaf(a,  ca,  acc[0]);   // d2 = <A, A>
            acc[1] = fmaf(a2, ca,  acc[1]);   // d3 = <A2, A>
            acc[2] = fmaf(a3, ca,  acc[2]);   // d4 = <A3, A>
            acc[3] = fmaf(a4, ca,  acc[3]);   // d5 = <A4, A>
            acc[4] = fmaf(a2, ca4, acc[4]);   // d6 = <A2, A4>
            acc[5] = fmaf(a3, ca4, acc[5]);   // d7 = <A3, A4>
            acc[6] = fmaf(a4, ca4, acc[6]);   // d8 = <A4, A4>
        }
        __syncthreads();
    }

#pragma unroll
    for (int p = 0; p < 7; p++) red[p][r][c] = acc[p];
    __syncthreads();

    if (r == 0) {
#pragma unroll
        for (int p = 0; p < 7; p++) {
            float s = 0.0f;
#pragma unroll
            for (int rr = 0; rr < 8; rr++) s += red[p][rr][c];
            atomicAdd(&g_D[(size_t)p * NB * N + (size_t)b * N + n0 + c], s);
        }
    }
}

__global__ __launch_bounds__(256) void combine_kernel(
    const float* __restrict__ A, const float* __restrict__ h,
    float* __restrict__ out)
{
    const int idx = blockIdx.x * blockDim.x + threadIdx.x;
    if (idx >= NB * N * 64) return;
    const int c = idx & 63;
    const int n = (idx >> 6) & (N - 1);
    const int b = idx >> 17;

    const float d1 = A[(size_t)b * NN + (size_t)n * N + n];
    float v = h[c] + h[64 + c] * d1;
#pragma unroll
    for (int t = 2; t <= 8; t++) {
        const float dt = g_D[(size_t)(t - 2) * NB * N + (size_t)b * N + n];
        v = fmaf(h[t * 64 + c], dt, v);
    }
    out[idx] = v;
}

// ---------------------------------------------------------------------------
// host
// ---------------------------------------------------------------------------
typedef CUresult (*PFN_tmap_encode)(
    CUtensorMap*, CUtensorMapDataType, cuuint32_t, void*,
    const cuuint64_t*, const cuuint64_t*, const cuuint32_t*, const cuuint32_t*,
    CUtensorMapInterleave, CUtensorMapSwizzle, CUtensorMapL2promotion,
    CUtensorMapFloatOOBfill);

static CUtensorMap make_map(PFN_tmap_encode enc, void* ptr, uint32_t box_rows) {
    CUtensorMap m{};
    cuuint64_t dims[3]    = {N, N, NB};
    cuuint64_t strides[2] = {(cuuint64_t)N * 2, (cuuint64_t)NN * 2};
    cuuint32_t box[3]     = {BK, box_rows, 1};
    cuuint32_t es[3]      = {1, 1, 1};
    enc(&m, CU_TENSOR_MAP_DATA_TYPE_BFLOAT16, 3, ptr, dims, strides, box, es,
        CU_TENSOR_MAP_INTERLEAVE_NONE, CU_TENSOR_MAP_SWIZZLE_128B,
        CU_TENSOR_MAP_L2_PROMOTION_L2_128B, CU_TENSOR_MAP_FLOAT_OOB_FILL_NONE);
    return m;
}

extern "C" void kernel_launch(void* const* d_in, const int* in_sizes, int n_in,
                              void* d_out, int out_size)
{
    const float* A = (const float*)d_in[0];   // [8, 2048, 2048]
    const float* h = (const float*)d_in[1];   // [9, 64]
    float* out = (float*)d_out;               // [8, 2048, 64]

    void *A2, *A3, *A4, *Ah, *Al, *AhT, *AlT, *A2h, *A2l, *A2hT, *A2lT;
    cudaGetSymbolAddress(&A2, g_A2);   cudaGetSymbolAddress(&A3, g_A3);
    cudaGetSymbolAddress(&A4, g_A4);
    cudaGetSymbolAddress(&Ah, g_Ah);   cudaGetSymbolAddress(&Al, g_Al);
    cudaGetSymbolAddress(&AhT, g_AhT); cudaGetSymbolAddress(&AlT, g_AlT);
    cudaGetSymbolAddress(&A2h, g_A2h); cudaGetSymbolAddress(&A2l, g_A2l);
    cudaGetSymbolAddress(&A2hT, g_A2hT); cudaGetSymbolAddress(&A2lT, g_A2lT);

    PFN_tmap_encode enc = nullptr;
    {
        void* fn = nullptr;
        cudaDriverEntryPointQueryResult qr;
        cudaGetDriverEntryPoint("cuTensorMapEncodeTiled", &fn,
                                cudaEnableDefault, &qr);
        enc = (PFN_tmap_encode)fn;
    }
    if (!enc) return;

    const CUtensorMap mAh   = make_map(enc, Ah,   BM);
    const CUtensorMap mAl   = make_map(enc, Al,   BM);
    const CUtensorMap mAhT  = make_map(enc, AhT,  BN);
    const CUtensorMap mAlT  = make_map(enc, AlT,  BN);
    const CUtensorMap mA2h  = make_map(enc, A2h,  BM);
    const CUtensorMap mA2l  = make_map(enc, A2l,  BM);
    const CUtensorMap mA2hT = make_map(enc, A2hT, BN);
    const CUtensorMap mA2lT = make_map(enc, A2lT, BN);

    cudaFuncSetAttribute(gemm_tma,
                         cudaFuncAttributeMaxDynamicSharedMemorySize, SMEM_GEMM);

    zeroD_kernel<<<(7 * NB * N + 255) / 256, 256>>>();

    split_both_kernel<<<dim3(N / 64, N / 64, NB), dim3(32, 8)>>>(
        A, (__nv_bfloat16*)Ah, (__nv_bfloat16*)Al,
        (__nv_bfloat16*)AhT, (__nv_bfloat16*)AlT);

    const dim3 gg(N / BN, N / BM, NB);
    // A2 = A @ A
    gemm_tma<<<gg, 256, SMEM_GEMM>>>(mAh, mAl, mAhT, mAlT, (float*)A2);

    split_both_kernel<<<dim3(N / 64, N / 64, NB), dim3(32, 8)>>>(
        (const float*)A2, (__nv_bfloat16*)A2h, (__nv_bfloat16*)A2l,
        (__nv_bfloat16*)A2hT, (__nv_bfloat16*)A2lT);

    // A3 = A2 @ A
    gemm_tma<<<gg, 256, SMEM_GEMM>>>(mA2h, mA2l, mAhT, mAlT, (float*)A3);
    // A4 = A2 @ A2
    gemm_tma<<<gg, 256, SMEM_GEMM>>>(mA2h, mA2l, mA2hT, mA2lT, (float*)A4);

    diag_kernel<<<dim3(N / 32, NB, KSPLIT), 256>>>(A);

    const int total = NB * N * 64;
    combine_kernel<<<(total + 255) / 256, 256>>>(A, h, out);
}